// round 6
// baseline (speedup 1.0000x reference)
#include <cuda_runtime.h>
#include <math.h>

#define NN 200000
#define FF 64
#define HH 256
#define DDIMC 768
#define NBUCK 65536
#define CAND_CAP 4096

// ---------------- scratch (device globals; no allocation allowed) ----------
__device__ int      g_deg[NN];
__device__ float    g_dis[NN];
__device__ float    g_acc[NN];
__device__ float    g_score[NN];
__device__ unsigned g_hist[NBUCK];
__device__ float    g_s[FF];
__device__ float    g_invnorm;
__device__ unsigned g_thresh;
__device__ int      g_cand_cnt;
__device__ unsigned g_cand_key[CAND_CAP];
__device__ int      g_cand_idx[CAND_CAP];
__device__ float    g_xt[FF * FF];
__device__ float    g_W[FF * FF];
__device__ float    g_gvec[HH];
__device__ float    g_dvec[HH];
__device__ float    g_h1[HH];

// ---------------- helpers --------------------------------------------------
__device__ __forceinline__ unsigned flipf(float f) {
    unsigned u = __float_as_uint(f);
    return (u & 0x80000000u) ? ~u : (u | 0x80000000u);
}
__device__ __forceinline__ float unflipf(unsigned u) {
    unsigned v = (u & 0x80000000u) ? (u ^ 0x80000000u) : ~u;
    return __uint_as_float(v);
}
__device__ __forceinline__ float warp_sum(float v) {
    for (int o = 16; o; o >>= 1) v += __shfl_xor_sync(0xffffffffu, v, o);
    return v;
}

// ---------------- kernels --------------------------------------------------
// init scratch + compute 1/||pool_w|| (warp 0 of block 0)
__global__ void k_zero(const float* __restrict__ pw) {
    int i = blockIdx.x * blockDim.x + threadIdx.x;
    int st = gridDim.x * blockDim.x;
    for (int n = i; n < NN; n += st) g_deg[n] = 1;          // self-loop folded in
    for (int b = i; b < NBUCK; b += st) g_hist[b] = 0u;
    if (i < FF) g_s[i] = 0.f;
    if (i == 0) g_cand_cnt = 0;
    if (blockIdx.x == 0 && threadIdx.x < 32) {
        int lane = threadIdx.x;
        float a = pw[lane], b = pw[lane + 32];
        float s = warp_sum(a * a + b * b);
        if (lane == 0) g_invnorm = 1.0f / sqrtf(s);
    }
}

__global__ void k_deg(const int* __restrict__ col, int E) {
    int i = blockIdx.x * blockDim.x + threadIdx.x;
    int st = gridDim.x * blockDim.x;
    for (int e = i; e < E; e += st) atomicAdd(&g_deg[col[e]], 1);
}

__global__ void k_dis() {
    int i = blockIdx.x * blockDim.x + threadIdx.x;
    int st = gridDim.x * blockDim.x;
    for (int n = i; n < NN; n += st) {
        float dv = rsqrtf((float)g_deg[n]);
        g_dis[n] = dv;
        g_acc[n] = dv * dv;                                 // self-loop contribution
    }
}

__global__ void k_acc(const int* __restrict__ row, const int* __restrict__ col, int E) {
    int i = blockIdx.x * blockDim.x + threadIdx.x;
    int st = gridDim.x * blockDim.x;
    for (int e = i; e < E; e += st) {
        int r = row[e], c = col[e];
        atomicAdd(&g_acc[r], g_dis[r] * g_dis[c]);
    }
}

// Fused pass over x: score (pool dot), 16-bit-key histogram, and s += acc[n]*x[n]
__global__ void k_xpass(const float* __restrict__ x, const float* __restrict__ pw) {
    const int lane = threadIdx.x & 31;
    const int warp = (blockIdx.x * blockDim.x + threadIdx.x) >> 5;
    const int nwarps = (gridDim.x * blockDim.x) >> 5;
    const float pw0 = pw[2 * lane], pw1 = pw[2 * lane + 1];
    const float inv = g_invnorm;
    float s0 = 0.f, s1 = 0.f;
    __shared__ float ssm[FF];
    if (threadIdx.x < FF) ssm[threadIdx.x] = 0.f;
    __syncthreads();
    for (int n = warp; n < NN; n += nwarps) {
        float2 xv = reinterpret_cast<const float2*>(x)[n * 32 + lane];
        float a = g_acc[n];
        s0 += a * xv.x;
        s1 += a * xv.y;
        float d = warp_sum(xv.x * pw0 + xv.y * pw1);
        if (lane == 0) {
            float sc = d * inv;
            g_score[n] = sc;
            atomicAdd(&g_hist[flipf(sc) >> 16], 1u);
        }
    }
    atomicAdd(&ssm[2 * lane], s0);
    atomicAdd(&ssm[2 * lane + 1], s1);
    __syncthreads();
    if (threadIdx.x < FF) atomicAdd(&g_s[threadIdx.x], ssm[threadIdx.x]);
}

// doc branch: d = relu(doc @ doc_fc_w.T + b) — independent of graph
__global__ void k_doc(const float* __restrict__ doc, const float* __restrict__ w,
                      const float* __restrict__ b) {
    int lane = threadIdx.x & 31;
    int o = (blockIdx.x * blockDim.x + threadIdx.x) >> 5;   // 32 blocks * 8 warps = 256
    if (o >= HH) return;
    const float* wr = w + o * DDIMC;
    float p = 0.f;
    for (int k = lane; k < DDIMC; k += 32) p += wr[k] * doc[k];
    p = warp_sum(p);
    if (lane == 0) {
        float v = p + b[o];
        g_dvec[o] = v > 0.f ? v : 0.f;
    }
}

// find highest 16-bit bucket whose suffix count >= 64
__global__ void k_thresh() {
    __shared__ unsigned chunk[256];
    __shared__ unsigned hc[256];
    __shared__ int tstar;
    __shared__ unsigned above;
    int tid = threadIdx.x;
    unsigned s = 0;
    const int base = tid * 256;
#pragma unroll 8
    for (int b = 0; b < 256; b++) s += g_hist[base + b];
    chunk[tid] = s;
    __syncthreads();
    if (tid == 0) {
        unsigned cum = 0;
        int t = 255;
        for (; t > 0; t--) {
            if (cum + chunk[t] >= 64u) break;
            cum += chunk[t];
        }
        tstar = t;
        above = cum;
    }
    __syncthreads();
    hc[tid] = g_hist[tstar * 256 + tid];
    __syncthreads();
    if (tid == 0) {
        unsigned cum = above;
        int b = 255;
        for (; b > 0; b--) {
            cum += hc[b];
            if (cum >= 64u) break;
        }
        g_thresh = ((unsigned)(tstar * 256 + b)) << 16;
    }
}

__global__ void k_gather() {
    int i = blockIdx.x * blockDim.x + threadIdx.x;
    int st = gridDim.x * blockDim.x;
    unsigned th = g_thresh;
    for (int n = i; n < NN; n += st) {
        unsigned u = flipf(g_score[n]);
        if (u >= th) {
            int p = atomicAdd(&g_cand_cnt, 1);
            if (p < CAND_CAP) {
                g_cand_key[p] = u;
                g_cand_idx[p] = n;
            }
        }
    }
}

// bitonic sort candidates descending (score desc, index asc), build x_tilde
__global__ void k_sort(const float* __restrict__ x) {
    __shared__ unsigned long long key[CAND_CAP];
    __shared__ int perm[FF];
    __shared__ float ts[FF];
    int cnt = g_cand_cnt;
    if (cnt > CAND_CAP) cnt = CAND_CAP;
    for (int i = threadIdx.x; i < CAND_CAP; i += blockDim.x)
        key[i] = (i < cnt)
                     ? (((unsigned long long)g_cand_key[i] << 32) |
                        (unsigned)(~(unsigned)g_cand_idx[i]))
                     : 0ULL;
    __syncthreads();
    for (int k = 2; k <= CAND_CAP; k <<= 1)
        for (int j = k >> 1; j > 0; j >>= 1) {
            for (int i = threadIdx.x; i < CAND_CAP; i += blockDim.x) {
                int ixj = i ^ j;
                if (ixj > i) {
                    bool up = ((i & k) == 0);               // descending overall
                    unsigned long long a = key[i], b = key[ixj];
                    if (up ? (a < b) : (a > b)) {
                        key[i] = b;
                        key[ixj] = a;
                    }
                }
            }
            __syncthreads();
        }
    if (threadIdx.x < FF) {
        unsigned long long c = key[threadIdx.x];
        int pidx = (int)(~(unsigned)(c & 0xFFFFFFFFu));
        if (pidx < 0 || pidx >= NN) pidx = 0;               // defensive clamp
        perm[threadIdx.x] = pidx;
        ts[threadIdx.x] = tanhf(unflipf((unsigned)(c >> 32)));
    }
    __syncthreads();
    for (int t = threadIdx.x; t < FF * FF; t += blockDim.x) {
        int i = t >> 6, f = t & 63;
        g_xt[t] = x[(long long)perm[i] * FF + f] * ts[i];
    }
}

// one-step GRU: W = (1-z)*tanh(xn + r*hn) + z*h0
// 256 threads: i = tid&63 (row), quarter = tid>>6; j = quarter + 4*m, m=0..15
// covers ALL 64 gate columns (R5 bug: m only ran 0..3 -> cols 16..63 never written)
__global__ void k_gru(const float* __restrict__ h0g, const float* __restrict__ wih,
                      const float* __restrict__ whh, const float* __restrict__ bih,
                      const float* __restrict__ bhh) {
    __shared__ float xt[FF][FF + 1];
    __shared__ float h0[FF][FF + 1];
    for (int t = threadIdx.x; t < FF * FF; t += blockDim.x) {
        int i = t >> 6, k = t & 63;
        xt[i][k] = g_xt[t];
        h0[i][k] = h0g[t];
    }
    __syncthreads();
    int i = threadIdx.x & 63;
    int q = threadIdx.x >> 6;
#pragma unroll 4
    for (int m = 0; m < 16; m++) {
        int j = q + 4 * m;                                  // uniform within warp
        const float* wr = wih + j * FF;
        const float* wz = wih + (j + 64) * FF;
        const float* wn = wih + (j + 128) * FF;
        const float* vr = whh + j * FF;
        const float* vz = whh + (j + 64) * FF;
        const float* vn = whh + (j + 128) * FF;
        float xr = bih[j], xz = bih[j + 64], xn = bih[j + 128];
        float hr = bhh[j], hz = bhh[j + 64], hn = bhh[j + 128];
#pragma unroll 8
        for (int k = 0; k < FF; k++) {
            float xv = xt[i][k], hv = h0[i][k];
            xr += xv * wr[k]; xz += xv * wz[k]; xn += xv * wn[k];
            hr += hv * vr[k]; hz += hv * vz[k]; hn += hv * vn[k];
        }
        float r = 1.f / (1.f + expf(-(xr + hr)));
        float z = 1.f / (1.f + expf(-(xz + hz)));
        float nc = tanhf(xn + r * hn);
        g_W[i * FF + j] = (1.f - z) * nc + z * h0[i][j];
    }
}

// pooled = (s @ W)/N ; g = pooled @ gnn_fc_w.T + b
__global__ void k_poolg(const float* __restrict__ w, const float* __restrict__ b) {
    __shared__ float p[FF];
    if (threadIdx.x < FF) {
        float a = 0.f;
        for (int k = 0; k < FF; k++) a += g_s[k] * g_W[k * FF + threadIdx.x];
        p[threadIdx.x] = a * (1.0f / (float)NN);
    }
    __syncthreads();
    int lane = threadIdx.x & 31, w8 = threadIdx.x >> 5;
    for (int o = w8; o < HH; o += 8) {
        float2 v = reinterpret_cast<const float2*>(w)[o * 32 + lane];
        float pp = warp_sum(v.x * p[2 * lane] + v.y * p[2 * lane + 1]);
        if (lane == 0) g_gvec[o] = pp + b[o];
    }
}

__device__ __forceinline__ float block_sum_256(float v, float* red) {
    int lane = threadIdx.x & 31, w = threadIdx.x >> 5;
    v = warp_sum(v);
    if (lane == 0) red[w] = v;
    __syncthreads();
    float r = (threadIdx.x < 8) ? red[threadIdx.x] : 0.f;
    if (threadIdx.x < 32) {
        for (int o = 4; o; o >>= 1) r += __shfl_xor_sync(0xffffffffu, r, o);
        if (threadIdx.x == 0) red[0] = r;
    }
    __syncthreads();
    float out = red[0];
    __syncthreads();
    return out;
}

// layernorm over [g|d] (redundant per block) + h1 = relu(ln @ fusion_w.T + b)
__global__ void k_h1(const float* __restrict__ lng, const float* __restrict__ lnb,
                     const float* __restrict__ fw, const float* __restrict__ fb) {
    __shared__ float ln[2 * HH];
    __shared__ float red[32];
    int tid = threadIdx.x;
    float f0 = g_gvec[tid];
    float f1 = g_dvec[tid];
    float mu = block_sum_256(f0 + f1, red) * (1.0f / 512.0f);
    float d0 = f0 - mu, d1 = f1 - mu;
    float var = block_sum_256(d0 * d0 + d1 * d1, red) * (1.0f / 512.0f);
    float rstd = rsqrtf(var + 1e-5f);
    ln[tid] = d0 * rstd * lng[tid] + lnb[tid];
    ln[tid + 256] = d1 * rstd * lng[tid + 256] + lnb[tid + 256];
    __syncthreads();
    int lane = tid & 31, w8 = tid >> 5;
    int o = blockIdx.x * 8 + w8;                            // 32 blocks * 8 warps = 256
    const float4* wr = reinterpret_cast<const float4*>(fw + o * 512);
    float p = 0.f;
#pragma unroll
    for (int it = 0; it < 4; it++) {
        float4 v4 = wr[lane + 32 * it];
        int k = (lane + 32 * it) * 4;
        p += v4.x * ln[k] + v4.y * ln[k + 1] + v4.z * ln[k + 2] + v4.w * ln[k + 3];
    }
    p = warp_sum(p);
    if (lane == 0) {
        float h = p + fb[o];
        g_h1[o] = h > 0.f ? h : 0.f;
    }
}

__global__ void k_out(const float* __restrict__ tw, const float* __restrict__ tb,
                      const float* __restrict__ timw, const float* __restrict__ timb,
                      float* __restrict__ out) {
    __shared__ float h1[HH];
    h1[threadIdx.x] = g_h1[threadIdx.x];
    __syncthreads();
    int lane = threadIdx.x & 31, w8 = threadIdx.x >> 5;
    for (int o = w8; o < 17; o += 8) {
        const float* wr = (o < 16) ? (tw + o * HH) : timw;
        float p = 0.f;
        for (int k = lane; k < HH; k += 32) p += wr[k] * h1[k];
        p = warp_sum(p);
        if (lane == 0) out[o] = p + ((o < 16) ? tb[o] : timb[0]);
    }
}

// ---------------- launch ----------------------------------------------------
extern "C" void kernel_launch(void* const* d_in, const int* in_sizes, int n_in,
                              void* d_out, int out_size) {
    const float* x        = (const float*)d_in[0];
    const int*   ei       = (const int*)d_in[1];
    const float* doc      = (const float*)d_in[2];
    const float* pool_w   = (const float*)d_in[3];
    const float* init_w   = (const float*)d_in[4];
    const float* gru_w_ih = (const float*)d_in[5];
    const float* gru_w_hh = (const float*)d_in[6];
    const float* gru_b_ih = (const float*)d_in[7];
    const float* gru_b_hh = (const float*)d_in[8];
    const float* gnn_fc_w = (const float*)d_in[9];
    const float* gnn_fc_b = (const float*)d_in[10];
    const float* doc_fc_w = (const float*)d_in[11];
    const float* doc_fc_b = (const float*)d_in[12];
    const float* ln_g     = (const float*)d_in[13];
    const float* ln_b     = (const float*)d_in[14];
    const float* fus_w    = (const float*)d_in[15];
    const float* fus_b    = (const float*)d_in[16];
    const float* task_w   = (const float*)d_in[17];
    const float* task_b   = (const float*)d_in[18];
    const float* time_w   = (const float*)d_in[19];
    const float* time_b   = (const float*)d_in[20];
    const int E = in_sizes[1] / 2;
    const int* row = ei;
    const int* col = ei + E;
    float* out = (float*)d_out;

    k_zero<<<256, 256>>>(pool_w);
    k_deg<<<2048, 256>>>(col, E);
    k_doc<<<32, 256>>>(doc, doc_fc_w, doc_fc_b);
    k_dis<<<784, 256>>>();
    k_acc<<<2048, 256>>>(row, col, E);
    k_xpass<<<296, 256>>>(x, pool_w);
    k_thresh<<<1, 256>>>();
    k_gather<<<784, 256>>>();
    k_sort<<<1, 1024>>>(x);
    k_gru<<<1, 256>>>(init_w, gru_w_ih, gru_w_hh, gru_b_ih, gru_b_hh);
    k_poolg<<<1, 256>>>(gnn_fc_w, gnn_fc_b);
    k_h1<<<32, 256>>>(ln_g, ln_b, fus_w, fus_b);
    k_out<<<1, 256>>>(task_w, task_b, time_w, time_b, out);
}

// round 9
// speedup vs baseline: 1.4483x; 1.4483x over previous
#include <cuda_runtime.h>
#include <math.h>
#include <stdint.h>

#define NN 200000
#define FF 64
#define HH 256
#define DDIMC 768
#define NBUCK 65536
#define CAND_CAP 2048

// ---------------- scratch (device globals; no allocation allowed) ----------
__device__ int      g_deg[NN];
__device__ float    g_acc[NN];        // sum of dis[col] per row (self-loop added later)
__device__ float    g_score[NN];
__device__ unsigned g_hist[NBUCK];
__device__ float    g_s[FF];
__device__ float    g_invnorm;
__device__ unsigned g_thresh;
__device__ int      g_cand_cnt;
__device__ unsigned g_done_x;
__device__ unsigned g_done_g;
__device__ unsigned g_cand_key[CAND_CAP];
__device__ int      g_cand_idx[CAND_CAP];
__device__ float    g_xt[FF * FF];

// ---------------- helpers --------------------------------------------------
__device__ __forceinline__ unsigned flipf(float f) {
    unsigned u = __float_as_uint(f);
    return (u & 0x80000000u) ? ~u : (u | 0x80000000u);
}
__device__ __forceinline__ float unflipf(unsigned u) {
    unsigned v = (u & 0x80000000u) ? (u ^ 0x80000000u) : ~u;
    return __uint_as_float(v);
}
__device__ __forceinline__ float warp_sum(float v) {
    for (int o = 16; o; o >>= 1) v += __shfl_xor_sync(0xffffffffu, v, o);
    return v;
}

// ---------------- kernels --------------------------------------------------
// init scratch + compute 1/||pool_w|| (warp 0 of block 0)
__global__ void k_zero(const float* __restrict__ pw) {
    int i = blockIdx.x * blockDim.x + threadIdx.x;
    int st = gridDim.x * blockDim.x;
    for (int n = i; n < NN; n += st) {
        g_deg[n] = 1;                                       // self-loop folded in
        g_acc[n] = 0.f;
    }
    for (int b = i; b < NBUCK; b += st) g_hist[b] = 0u;
    if (i < FF) g_s[i] = 0.f;
    if (i == 0) { g_cand_cnt = 0; g_done_x = 0u; g_done_g = 0u; }
    if (blockIdx.x == 0 && threadIdx.x < 32) {
        int lane = threadIdx.x;
        float a = pw[lane], b = pw[lane + 32];
        float s = warp_sum(a * a + b * b);
        if (lane == 0) g_invnorm = 1.0f / sqrtf(s);
    }
}

__global__ void k_deg(const int* __restrict__ col, int E) {
    int i = blockIdx.x * blockDim.x + threadIdx.x;
    int st = gridDim.x * blockDim.x;
    if ((E & 3) == 0 && ((((uintptr_t)col) & 15u) == 0)) {
        const int4* c4 = reinterpret_cast<const int4*>(col);
        int nv = E >> 2;
        for (int v = i; v < nv; v += st) {
            int4 c = c4[v];
            atomicAdd(&g_deg[c.x], 1);
            atomicAdd(&g_deg[c.y], 1);
            atomicAdd(&g_deg[c.z], 1);
            atomicAdd(&g_deg[c.w], 1);
        }
    } else {
        for (int e = i; e < E; e += st) atomicAdd(&g_deg[col[e]], 1);
    }
}

// accsum[row] += rsqrt(deg[col])  (dis[row] factored out; applied in k_xpass)
__global__ void k_acc(const int* __restrict__ row, const int* __restrict__ col, int E) {
    int i = blockIdx.x * blockDim.x + threadIdx.x;
    int st = gridDim.x * blockDim.x;
    if ((E & 3) == 0 && ((((uintptr_t)col) & 15u) == 0) && ((((uintptr_t)row) & 15u) == 0)) {
        const int4* c4 = reinterpret_cast<const int4*>(col);
        const int4* r4 = reinterpret_cast<const int4*>(row);
        int nv = E >> 2;
        for (int v = i; v < nv; v += st) {
            int4 c = c4[v];
            int4 r = r4[v];
            float d0 = rsqrtf((float)g_deg[c.x]);
            float d1 = rsqrtf((float)g_deg[c.y]);
            float d2 = rsqrtf((float)g_deg[c.z]);
            float d3 = rsqrtf((float)g_deg[c.w]);
            atomicAdd(&g_acc[r.x], d0);
            atomicAdd(&g_acc[r.y], d1);
            atomicAdd(&g_acc[r.z], d2);
            atomicAdd(&g_acc[r.w], d3);
        }
    } else {
        for (int e = i; e < E; e += st)
            atomicAdd(&g_acc[row[e]], rsqrtf((float)g_deg[col[e]]));
    }
}

// Fused pass over x: score + 16-bit-key histogram + s += a[n]*x[n].
// Last finishing block computes the top-64 threshold from the histogram.
__global__ void k_xpass(const float* __restrict__ x, const float* __restrict__ pw) {
    __shared__ float ssm[FF];
    __shared__ unsigned chunk[256];
    __shared__ unsigned hc[256];
    __shared__ int sh_last;
    __shared__ int tstar;
    __shared__ unsigned above;
    const int tid = threadIdx.x;
    const int lane = tid & 31;
    const int warp = (blockIdx.x * blockDim.x + tid) >> 5;
    const int nwarps = (gridDim.x * blockDim.x) >> 5;
    const float pw0 = pw[2 * lane], pw1 = pw[2 * lane + 1];
    const float inv = g_invnorm;
    float s0 = 0.f, s1 = 0.f;
    if (tid < FF) ssm[tid] = 0.f;
    __syncthreads();
    for (int n = warp; n < NN; n += nwarps) {
        float2 xv = reinterpret_cast<const float2*>(x)[n * 32 + lane];
        float dv = rsqrtf((float)g_deg[n]);
        float a = dv * (g_acc[n] + dv);                    // dis[n]*(accsum + dis[n])
        s0 += a * xv.x;
        s1 += a * xv.y;
        float d = warp_sum(xv.x * pw0 + xv.y * pw1);
        if (lane == 0) {
            float sc = d * inv;
            g_score[n] = sc;
            atomicAdd(&g_hist[flipf(sc) >> 16], 1u);
        }
    }
    atomicAdd(&ssm[2 * lane], s0);
    atomicAdd(&ssm[2 * lane + 1], s1);
    __syncthreads();
    if (tid < FF) atomicAdd(&g_s[tid], ssm[tid]);
    // ---- last-block-done: compute threshold from completed histogram ----
    __threadfence();
    __syncthreads();
    if (tid == 0) sh_last = (atomicAdd(&g_done_x, 1u) == gridDim.x - 1u) ? 1 : 0;
    __syncthreads();
    if (!sh_last) return;
    __threadfence();
    unsigned s = 0;
    const int base = tid * 256;
#pragma unroll 8
    for (int b = 0; b < 256; b++) s += g_hist[base + b];
    chunk[tid] = s;
    __syncthreads();
    if (tid == 0) {
        unsigned cum = 0;
        int t = 255;
        for (; t > 0; t--) {
            if (cum + chunk[t] >= 64u) break;
            cum += chunk[t];
        }
        tstar = t;
        above = cum;
    }
    __syncthreads();
    hc[tid] = g_hist[tstar * 256 + tid];
    __syncthreads();
    if (tid == 0) {
        unsigned cum = above;
        int b = 255;
        for (; b > 0; b--) {
            cum += hc[b];
            if (cum >= 64u) break;
        }
        g_thresh = ((unsigned)(tstar * 256 + b)) << 16;
    }
}

// gather candidates >= threshold; last block does rank-selection + builds x_tilde
__global__ void k_gather(const float* __restrict__ x) {
    __shared__ int sh_last;
    __shared__ unsigned long long ck[CAND_CAP];
    __shared__ unsigned long long sel[FF];
    __shared__ int perm[FF];
    __shared__ float ts[FF];
    const int tid = threadIdx.x;
    int i = blockIdx.x * blockDim.x + tid;
    int st = gridDim.x * blockDim.x;
    unsigned th = g_thresh;
    for (int n = i; n < NN; n += st) {
        unsigned u = flipf(g_score[n]);
        if (u >= th) {
            int p = atomicAdd(&g_cand_cnt, 1);
            if (p < CAND_CAP) {
                g_cand_key[p] = u;
                g_cand_idx[p] = n;
            }
        }
    }
    __threadfence();
    __syncthreads();
    if (tid == 0) sh_last = (atomicAdd(&g_done_g, 1u) == gridDim.x - 1u) ? 1 : 0;
    __syncthreads();
    if (!sh_last) return;
    __threadfence();
    int cnt = g_cand_cnt;
    if (cnt > CAND_CAP) cnt = CAND_CAP;
    for (int c = tid; c < cnt; c += blockDim.x)
        ck[c] = (((unsigned long long)g_cand_key[c]) << 32) |
                (unsigned)(~(unsigned)g_cand_idx[c]);
    __syncthreads();
    // rank-based top-64 selection (composite keys are unique)
    for (int c = tid; c < cnt; c += blockDim.x) {
        unsigned long long mine = ck[c];
        int r = 0;
        for (int j = 0; j < cnt; j++) r += (ck[j] > mine) ? 1 : 0;
        if (r < FF) sel[r] = mine;
    }
    __syncthreads();
    if (tid < FF) {
        unsigned long long c = sel[tid];
        int pidx = (int)(~(unsigned)(c & 0xFFFFFFFFu));
        if (pidx < 0 || pidx >= NN) pidx = 0;               // defensive clamp
        perm[tid] = pidx;
        ts[tid] = tanhf(unflipf((unsigned)(c >> 32)));
    }
    __syncthreads();
    for (int t = tid; t < FF * FF; t += blockDim.x) {
        int r = t >> 6, f = t & 63;
        g_xt[t] = x[(long long)perm[r] * FF + f] * ts[r];
    }
}

__device__ __forceinline__ float block_sum_512(float v, float* red) {
    int lane = threadIdx.x & 31, w = threadIdx.x >> 5;
    v = warp_sum(v);
    if (lane == 0) red[w] = v;
    __syncthreads();
    if (threadIdx.x < 32) {
        float r = (threadIdx.x < 16) ? red[threadIdx.x] : 0.f;
        for (int o = 8; o; o >>= 1) r += __shfl_xor_sync(0xffffffffu, r, o);
        if (threadIdx.x == 0) red[0] = r;
    }
    __syncthreads();
    float out = red[0];
    __syncthreads();
    return out;
}

// tail: doc FC + GRU + pooled@W + gnn FC + layernorm + fusion FC + heads
__global__ void __launch_bounds__(512) k_tail(
    const float* __restrict__ doc, const float* __restrict__ dw, const float* __restrict__ db,
    const float* __restrict__ h0g, const float* __restrict__ wih, const float* __restrict__ whh,
    const float* __restrict__ bih, const float* __restrict__ bhh,
    const float* __restrict__ gw, const float* __restrict__ gb,
    const float* __restrict__ lng, const float* __restrict__ lnb,
    const float* __restrict__ fw, const float* __restrict__ fb,
    const float* __restrict__ tw, const float* __restrict__ tb,
    const float* __restrict__ timw, const float* __restrict__ timb,
    float* __restrict__ out)
{
    __shared__ float xt[FF][FF + 1];                       // x_tilde, then reused for W
    __shared__ float h0[FF][FF + 1];
    __shared__ float ssh[FF];
    __shared__ float pv[FF];
    __shared__ float s_d[HH];
    __shared__ float s_g[HH];
    __shared__ float ln[2 * HH];
    __shared__ float s_h1[HH];
    __shared__ float red[16];
    const int tid = threadIdx.x;
    const int lane = tid & 31;
    const int wp = tid >> 5;                               // 0..15

    // A: doc branch d = relu(doc @ dw.T + db)
    for (int o = wp; o < HH; o += 16) {
        const float* wr = dw + o * DDIMC;
        float p = 0.f;
        for (int k = lane; k < DDIMC; k += 32) p += wr[k] * doc[k];
        p = warp_sum(p);
        if (lane == 0) {
            float v = p + db[o];
            s_d[o] = v > 0.f ? v : 0.f;
        }
    }
    // load x_tilde and h0 into shared
    for (int t = tid; t < FF * FF; t += 512) {
        int r = t >> 6, k = t & 63;
        xt[r][k] = g_xt[t];
        h0[r][k] = h0g[t];
    }
    __syncthreads();

    // B: GRU  (i = row, j = q + 8m covers all 64 columns)
    const int i = tid & 63;
    const int q = tid >> 6;                                // 0..7, uniform within warp
    float Wloc[8];
#pragma unroll
    for (int m = 0; m < 8; m++) {
        int j = q + 8 * m;
        const float* wr = wih + j * FF;
        const float* wz = wih + (j + 64) * FF;
        const float* wn = wih + (j + 128) * FF;
        const float* vr = whh + j * FF;
        const float* vz = whh + (j + 64) * FF;
        const float* vn = whh + (j + 128) * FF;
        float xr = bih[j], xz = bih[j + 64], xn = bih[j + 128];
        float hr = bhh[j], hz = bhh[j + 64], hn = bhh[j + 128];
#pragma unroll 8
        for (int k = 0; k < FF; k++) {
            float xv = xt[i][k], hv = h0[i][k];
            xr += xv * wr[k]; xz += xv * wz[k]; xn += xv * wn[k];
            hr += hv * vr[k]; hz += hv * vz[k]; hn += hv * vn[k];
        }
        float r = 1.f / (1.f + expf(-(xr + hr)));
        float z = 1.f / (1.f + expf(-(xz + hz)));
        float nc = tanhf(xn + r * hn);
        Wloc[m] = (1.f - z) * nc + z * h0[i][j];
    }
    __syncthreads();                                       // all xt reads done
#pragma unroll
    for (int m = 0; m < 8; m++) xt[i][q + 8 * m] = Wloc[m]; // xt now holds W
    if (tid < FF) ssh[tid] = g_s[tid];
    __syncthreads();

    // C: pooled = (s @ W)/N ; g = pooled @ gw.T + gb
    if (tid < FF) {
        float a = 0.f;
#pragma unroll 8
        for (int k = 0; k < FF; k++) a += ssh[k] * xt[k][tid];
        pv[tid] = a * (1.0f / (float)NN);
    }
    __syncthreads();
    for (int o = wp; o < HH; o += 16) {
        float2 v = reinterpret_cast<const float2*>(gw)[o * 32 + lane];
        float pp = warp_sum(v.x * pv[2 * lane] + v.y * pv[2 * lane + 1]);
        if (lane == 0) s_g[o] = pp + gb[o];
    }
    __syncthreads();

    // D: layernorm over [g | d] (512 elems, one per thread)
    float f0 = (tid < HH) ? s_g[tid] : s_d[tid - HH];
    float mu = block_sum_512(f0, red) * (1.0f / 512.0f);
    float d0 = f0 - mu;
    float var = block_sum_512(d0 * d0, red) * (1.0f / 512.0f);
    float rstd = rsqrtf(var + 1e-5f);
    ln[tid] = d0 * rstd * lng[tid] + lnb[tid];
    __syncthreads();

    // E: h1 = relu(ln @ fw.T + fb)
    for (int o = wp; o < HH; o += 16) {
        const float4* wr = reinterpret_cast<const float4*>(fw + o * 512);
        float p = 0.f;
#pragma unroll
        for (int it = 0; it < 4; it++) {
            float4 v4 = wr[lane + 32 * it];
            int k = (lane + 32 * it) * 4;
            p += v4.x * ln[k] + v4.y * ln[k + 1] + v4.z * ln[k + 2] + v4.w * ln[k + 3];
        }
        p = warp_sum(p);
        if (lane == 0) {
            float h = p + fb[o];
            s_h1[o] = h > 0.f ? h : 0.f;
        }
    }
    __syncthreads();

    // F: heads
    for (int o = wp; o < 17; o += 16) {
        const float* wr = (o < 16) ? (tw + o * HH) : timw;
        float p = 0.f;
        for (int k = lane; k < HH; k += 32) p += wr[k] * s_h1[k];
        p = warp_sum(p);
        if (lane == 0) out[o] = p + ((o < 16) ? tb[o] : timb[0]);
    }
}

// ---------------- launch ----------------------------------------------------
extern "C" void kernel_launch(void* const* d_in, const int* in_sizes, int n_in,
                              void* d_out, int out_size) {
    const float* x        = (const float*)d_in[0];
    const int*   ei       = (const int*)d_in[1];
    const float* doc      = (const float*)d_in[2];
    const float* pool_w   = (const float*)d_in[3];
    const float* init_w   = (const float*)d_in[4];
    const float* gru_w_ih = (const float*)d_in[5];
    const float* gru_w_hh = (const float*)d_in[6];
    const float* gru_b_ih = (const float*)d_in[7];
    const float* gru_b_hh = (const float*)d_in[8];
    const float* gnn_fc_w = (const float*)d_in[9];
    const float* gnn_fc_b = (const float*)d_in[10];
    const float* doc_fc_w = (const float*)d_in[11];
    const float* doc_fc_b = (const float*)d_in[12];
    const float* ln_g     = (const float*)d_in[13];
    const float* ln_b     = (const float*)d_in[14];
    const float* fus_w    = (const float*)d_in[15];
    const float* fus_b    = (const float*)d_in[16];
    const float* task_w   = (const float*)d_in[17];
    const float* task_b   = (const float*)d_in[18];
    const float* time_w   = (const float*)d_in[19];
    const float* time_b   = (const float*)d_in[20];
    const int E = in_sizes[1] / 2;
    const int* row = ei;
    const int* col = ei + E;
    float* out = (float*)d_out;

    k_zero<<<256, 256>>>(pool_w);
    k_deg<<<2048, 256>>>(col, E);
    k_acc<<<2048, 256>>>(row, col, E);
    k_xpass<<<592, 256>>>(x, pool_w);
    k_gather<<<784, 256>>>(x);
    k_tail<<<1, 512>>>(doc, doc_fc_w, doc_fc_b, init_w, gru_w_ih, gru_w_hh,
                       gru_b_ih, gru_b_hh, gnn_fc_w, gnn_fc_b, ln_g, ln_b,
                       fus_w, fus_b, task_w, task_b, time_w, time_b, out);
}

// round 10
// speedup vs baseline: 1.5660x; 1.0812x over previous
#include <cuda_runtime.h>
#include <math.h>
#include <stdint.h>

#define NN 200000
#define FF 64
#define HH 256
#define DDIMC 768
#define NBUCK 65536
#define CAND_CAP 2048

// ---------------- scratch (device globals; no allocation allowed) ----------
__device__ int      g_deg[NN];
__device__ float    g_acc[NN];        // sum of dis[col] per row (self-loop added in xpass)
__device__ float    g_score[NN];
__device__ unsigned g_hist[NBUCK];
__device__ float    g_s[FF];
__device__ float    g_dvec[HH];
__device__ float    g_invnorm;
__device__ unsigned g_thresh;
__device__ int      g_cand_cnt;
__device__ unsigned g_done_x;
__device__ unsigned g_done_g;
__device__ unsigned g_cand_key[CAND_CAP];
__device__ int      g_cand_idx[CAND_CAP];

// ---------------- helpers --------------------------------------------------
__device__ __forceinline__ unsigned flipf(float f) {
    unsigned u = __float_as_uint(f);
    return (u & 0x80000000u) ? ~u : (u | 0x80000000u);
}
__device__ __forceinline__ float unflipf(unsigned u) {
    unsigned v = (u & 0x80000000u) ? (u ^ 0x80000000u) : ~u;
    return __uint_as_float(v);
}
__device__ __forceinline__ float warp_sum(float v) {
    for (int o = 16; o; o >>= 1) v += __shfl_xor_sync(0xffffffffu, v, o);
    return v;
}

// ---------------- kernels --------------------------------------------------
// blocks 0..255: init scratch (+ invnorm in block 0); blocks 256..287: doc FC
__global__ void k_zero(const float* __restrict__ pw, const float* __restrict__ doc,
                       const float* __restrict__ dw, const float* __restrict__ db) {
    if (blockIdx.x >= 256) {
        int lane = threadIdx.x & 31;
        int o = (int)(blockIdx.x - 256) * 8 + (threadIdx.x >> 5);   // 0..255
        const float* wr = dw + o * DDIMC;
        float p = 0.f;
        for (int k = lane; k < DDIMC; k += 32) p += wr[k] * doc[k];
        p = warp_sum(p);
        if (lane == 0) {
            float v = p + db[o];
            g_dvec[o] = v > 0.f ? v : 0.f;
        }
        return;
    }
    int i = blockIdx.x * blockDim.x + threadIdx.x;
    const int st = 256 * 256;
    for (int n = i; n < NN; n += st) {
        g_deg[n] = 1;                                       // self-loop folded in
        g_acc[n] = 0.f;
    }
    for (int b = i; b < NBUCK; b += st) g_hist[b] = 0u;
    if (i < FF) g_s[i] = 0.f;
    if (i == 0) { g_cand_cnt = 0; g_done_x = 0u; g_done_g = 0u; }
    if (blockIdx.x == 0 && threadIdx.x < 32) {
        int lane = threadIdx.x;
        float a = pw[lane], b = pw[lane + 32];
        float s = warp_sum(a * a + b * b);
        if (lane == 0) g_invnorm = 1.0f / sqrtf(s);
    }
}

__global__ void k_deg(const int* __restrict__ col, int E) {
    int i = blockIdx.x * blockDim.x + threadIdx.x;
    int st = gridDim.x * blockDim.x;
    if ((E & 3) == 0 && ((((uintptr_t)col) & 15u) == 0)) {
        const int4* c4 = reinterpret_cast<const int4*>(col);
        int nv = E >> 2;
#pragma unroll 2
        for (int v = i; v < nv; v += st) {
            int4 c = c4[v];
            atomicAdd(&g_deg[c.x], 1);
            atomicAdd(&g_deg[c.y], 1);
            atomicAdd(&g_deg[c.z], 1);
            atomicAdd(&g_deg[c.w], 1);
        }
    } else {
        for (int e = i; e < E; e += st) atomicAdd(&g_deg[col[e]], 1);
    }
}

// accsum[row] += rsqrt(deg[col])  (dis[row] factored out; applied in k_xpass)
__global__ void k_acc(const int* __restrict__ row, const int* __restrict__ col, int E) {
    int i = blockIdx.x * blockDim.x + threadIdx.x;
    int st = gridDim.x * blockDim.x;
    if ((E & 3) == 0 && ((((uintptr_t)col) & 15u) == 0) && ((((uintptr_t)row) & 15u) == 0)) {
        const int4* c4 = reinterpret_cast<const int4*>(col);
        const int4* r4 = reinterpret_cast<const int4*>(row);
        int nv = E >> 2;
#pragma unroll 2
        for (int v = i; v < nv; v += st) {
            int4 c = c4[v];
            int4 r = r4[v];
            float d0 = rsqrtf((float)g_deg[c.x]);
            float d1 = rsqrtf((float)g_deg[c.y]);
            float d2 = rsqrtf((float)g_deg[c.z]);
            float d3 = rsqrtf((float)g_deg[c.w]);
            atomicAdd(&g_acc[r.x], d0);
            atomicAdd(&g_acc[r.y], d1);
            atomicAdd(&g_acc[r.z], d2);
            atomicAdd(&g_acc[r.w], d3);
        }
    } else {
        for (int e = i; e < E; e += st)
            atomicAdd(&g_acc[row[e]], rsqrtf((float)g_deg[col[e]]));
    }
}

// Fused pass over x, 8 nodes per warp-iteration (MLP/ILP):
// score + 16-bit-key histogram + s += a[n]*x[n]; last block derives top-64 threshold.
__global__ void k_xpass(const float* __restrict__ x, const float* __restrict__ pw) {
    __shared__ float ssm[FF];
    __shared__ unsigned chunk[256];
    __shared__ unsigned hc[256];
    __shared__ int sh_last;
    __shared__ int tstar;
    __shared__ unsigned above;
    const int tid = threadIdx.x;
    const int lane = tid & 31;
    const int warp = (blockIdx.x * blockDim.x + tid) >> 5;
    const int nwarps = (gridDim.x * blockDim.x) >> 5;
    const float pw0 = pw[2 * lane], pw1 = pw[2 * lane + 1];
    const float inv = g_invnorm;
    float s0 = 0.f, s1 = 0.f;
    if (tid < FF) ssm[tid] = 0.f;
    __syncthreads();
    const float2* x2 = reinterpret_cast<const float2*>(x);
    for (int g = warp; g < NN / 8; g += nwarps) {           // NN % 8 == 0
        const int base = g * 8;
        float2 xv[8];
        float aa[8], sc[8];
#pragma unroll
        for (int b = 0; b < 8; b++) xv[b] = x2[(base + b) * 32 + lane];
#pragma unroll
        for (int b = 0; b < 8; b++) {
            float dv = rsqrtf((float)g_deg[base + b]);      // broadcast loads
            aa[b] = dv * (g_acc[base + b] + dv);
        }
#pragma unroll
        for (int b = 0; b < 8; b++) {
            s0 += aa[b] * xv[b].x;
            s1 += aa[b] * xv[b].y;
            sc[b] = xv[b].x * pw0 + xv[b].y * pw1;
        }
#pragma unroll
        for (int o = 16; o; o >>= 1)
#pragma unroll
            for (int b = 0; b < 8; b++) sc[b] += __shfl_xor_sync(0xffffffffu, sc[b], o);
        if (lane == 0) {
#pragma unroll
            for (int b = 0; b < 8; b++) {
                float s = sc[b] * inv;
                g_score[base + b] = s;
                atomicAdd(&g_hist[flipf(s) >> 16], 1u);
            }
        }
    }
    atomicAdd(&ssm[2 * lane], s0);
    atomicAdd(&ssm[2 * lane + 1], s1);
    __syncthreads();
    if (tid < FF) atomicAdd(&g_s[tid], ssm[tid]);
    // ---- last-block-done: compute threshold from completed histogram ----
    __threadfence();
    __syncthreads();
    if (tid == 0) sh_last = (atomicAdd(&g_done_x, 1u) == gridDim.x - 1u) ? 1 : 0;
    __syncthreads();
    if (!sh_last) return;
    __threadfence();
    unsigned s = 0;
    const int base = tid * 256;
#pragma unroll 8
    for (int b = 0; b < 256; b++) s += g_hist[base + b];
    chunk[tid] = s;
    __syncthreads();
    if (tid == 0) {
        unsigned cum = 0;
        int t = 255;
        for (; t > 0; t--) {
            if (cum + chunk[t] >= 64u) break;
            cum += chunk[t];
        }
        tstar = t;
        above = cum;
    }
    __syncthreads();
    hc[tid] = g_hist[tstar * 256 + tid];
    __syncthreads();
    if (tid == 0) {
        unsigned cum = above;
        int b = 255;
        for (; b > 0; b--) {
            cum += hc[b];
            if (cum >= 64u) break;
        }
        g_thresh = ((unsigned)(tstar * 256 + b)) << 16;
    }
}

__device__ __forceinline__ float block_sum_512(float v, volatile float* red) {
    int lane = threadIdx.x & 31, w = threadIdx.x >> 5;
    v = warp_sum(v);
    if (lane == 0) red[w] = v;
    __syncthreads();
    if (threadIdx.x < 32) {
        float r = (threadIdx.x < 16) ? red[threadIdx.x] : 0.f;
        for (int o = 8; o; o >>= 1) r += __shfl_xor_sync(0xffffffffu, r, o);
        if (threadIdx.x == 0) red[0] = r;
    }
    __syncthreads();
    float out = red[0];
    __syncthreads();
    return out;
}

// gather candidates >= threshold; last block: top-64 selection + ENTIRE tail
// (x_tilde -> GRU -> pooled@W -> gnn FC -> layernorm -> fusion FC -> heads)
__global__ void __launch_bounds__(512) k_gather(
    const float* __restrict__ x,
    const float* __restrict__ h0g, const float* __restrict__ wih, const float* __restrict__ whh,
    const float* __restrict__ bih, const float* __restrict__ bhh,
    const float* __restrict__ gw, const float* __restrict__ gb,
    const float* __restrict__ lng, const float* __restrict__ lnb,
    const float* __restrict__ fw, const float* __restrict__ fb,
    const float* __restrict__ tw, const float* __restrict__ tb,
    const float* __restrict__ timw, const float* __restrict__ timb,
    float* __restrict__ out)
{
    __shared__ __align__(16) unsigned char sb[39040];
    // region aliases (ck dead before xt is written)
    unsigned long long* ck  = reinterpret_cast<unsigned long long*>(sb);          // 16384B
    float (*xt)[FF + 1]     = reinterpret_cast<float (*)[FF + 1]>(sb);            // 16640B
    float (*h0)[FF + 1]     = reinterpret_cast<float (*)[FF + 1]>(sb + 16640);    // 16640B
    unsigned long long* sel = reinterpret_cast<unsigned long long*>(sb + 33280);  // 512B
    int*   perm             = reinterpret_cast<int*>(sb + 33792);                 // 256B
    float* ts               = reinterpret_cast<float*>(sb + 34048);               // 256B
    float* s_g              = reinterpret_cast<float*>(sb + 34304);               // 1024B
    float* ln               = reinterpret_cast<float*>(sb + 35328);               // 2048B
    float* s_h1             = reinterpret_cast<float*>(sb + 37376);               // 1024B
    float* ssh              = reinterpret_cast<float*>(sb + 38400);               // 256B
    float* pv               = reinterpret_cast<float*>(sb + 38656);               // 256B
    float* red              = reinterpret_cast<float*>(sb + 38912);               // 64B
    __shared__ int sh_last;

    const int tid = threadIdx.x;
    const int lane = tid & 31;
    const int wp = tid >> 5;                                // 0..15
    {
        int i = blockIdx.x * blockDim.x + tid;
        int st = gridDim.x * blockDim.x;
        unsigned th = g_thresh;
        for (int n = i; n < NN; n += st) {
            unsigned u = flipf(g_score[n]);
            if (u >= th) {
                int p = atomicAdd(&g_cand_cnt, 1);
                if (p < CAND_CAP) {
                    g_cand_key[p] = u;
                    g_cand_idx[p] = n;
                }
            }
        }
    }
    __threadfence();
    __syncthreads();
    if (tid == 0) sh_last = (atomicAdd(&g_done_g, 1u) == gridDim.x - 1u) ? 1 : 0;
    __syncthreads();
    if (!sh_last) return;
    __threadfence();

    // ---- top-64 rank selection (composite keys unique) ----
    int cnt = g_cand_cnt;
    if (cnt > CAND_CAP) cnt = CAND_CAP;
    for (int c = tid; c < cnt; c += 512)
        ck[c] = (((unsigned long long)g_cand_key[c]) << 32) |
                (unsigned)(~(unsigned)g_cand_idx[c]);
    __syncthreads();
    for (int c = tid; c < cnt; c += 512) {
        unsigned long long mine = ck[c];
        int r = 0;
        for (int j = 0; j < cnt; j++) r += (ck[j] > mine) ? 1 : 0;
        if (r < FF) sel[r] = mine;
    }
    __syncthreads();                                        // ck dead after this
    if (tid < FF) {
        unsigned long long c = sel[tid];
        int pidx = (int)(~(unsigned)(c & 0xFFFFFFFFu));
        if (pidx < 0 || pidx >= NN) pidx = 0;               // defensive clamp
        perm[tid] = pidx;
        ts[tid] = tanhf(unflipf((unsigned)(c >> 32)));
    }
    if (tid < FF) ssh[tid] = g_s[tid];
    __syncthreads();
    // build x_tilde (into ck's region) + load h0
    for (int t = tid; t < FF * FF; t += 512) {
        int r = t >> 6, f = t & 63;
        xt[r][f] = x[(long long)perm[r] * FF + f] * ts[r];
        h0[r][f] = h0g[t];
    }
    __syncthreads();

    // ---- GRU: W = (1-z)*tanh(xn + r*hn) + z*h0 ----
    const int i = tid & 63;
    const int q = tid >> 6;                                 // 0..7, uniform within warp
    float Wloc[8];
#pragma unroll
    for (int m = 0; m < 8; m++) {
        int j = q + 8 * m;
        const float* wr = wih + j * FF;
        const float* wz = wih + (j + 64) * FF;
        const float* wn = wih + (j + 128) * FF;
        const float* vr = whh + j * FF;
        const float* vz = whh + (j + 64) * FF;
        const float* vn = whh + (j + 128) * FF;
        float xr = bih[j], xz = bih[j + 64], xn = bih[j + 128];
        float hr = bhh[j], hz = bhh[j + 64], hn = bhh[j + 128];
#pragma unroll 8
        for (int k = 0; k < FF; k++) {
            float xv = xt[i][k], hv = h0[i][k];
            xr += xv * wr[k]; xz += xv * wz[k]; xn += xv * wn[k];
            hr += hv * vr[k]; hz += hv * vz[k]; hn += hv * vn[k];
        }
        float r = 1.f / (1.f + expf(-(xr + hr)));
        float z = 1.f / (1.f + expf(-(xz + hz)));
        float nc = tanhf(xn + r * hn);
        Wloc[m] = (1.f - z) * nc + z * h0[i][j];
    }
    __syncthreads();                                        // all xt reads done
#pragma unroll
    for (int m = 0; m < 8; m++) xt[i][q + 8 * m] = Wloc[m]; // xt now holds W
    __syncthreads();

    // ---- pooled = (s @ W)/N ; g = pooled @ gw.T + gb ----
    if (tid < FF) {
        float a = 0.f;
#pragma unroll 8
        for (int k = 0; k < FF; k++) a += ssh[k] * xt[k][tid];
        pv[tid] = a * (1.0f / (float)NN);
    }
    __syncthreads();
    for (int o = wp; o < HH; o += 16) {
        float2 v = reinterpret_cast<const float2*>(gw)[o * 32 + lane];
        float pp = warp_sum(v.x * pv[2 * lane] + v.y * pv[2 * lane + 1]);
        if (lane == 0) s_g[o] = pp + gb[o];
    }
    __syncthreads();

    // ---- layernorm over [g | d] ----
    float f0 = (tid < HH) ? s_g[tid] : g_dvec[tid - HH];
    float mu = block_sum_512(f0, red) * (1.0f / 512.0f);
    float d0 = f0 - mu;
    float var = block_sum_512(d0 * d0, red) * (1.0f / 512.0f);
    float rstd = rsqrtf(var + 1e-5f);
    ln[tid] = d0 * rstd * lng[tid] + lnb[tid];
    __syncthreads();

    // ---- h1 = relu(ln @ fw.T + fb) ----
    for (int o = wp; o < HH; o += 16) {
        const float4* wr = reinterpret_cast<const float4*>(fw + o * 512);
        float p = 0.f;
#pragma unroll
        for (int it = 0; it < 4; it++) {
            float4 v4 = wr[lane + 32 * it];
            int k = (lane + 32 * it) * 4;
            p += v4.x * ln[k] + v4.y * ln[k + 1] + v4.z * ln[k + 2] + v4.w * ln[k + 3];
        }
        p = warp_sum(p);
        if (lane == 0) {
            float h = p + fb[o];
            s_h1[o] = h > 0.f ? h : 0.f;
        }
    }
    __syncthreads();

    // ---- heads ----
    for (int o = wp; o < 17; o += 16) {
        const float* wr = (o < 16) ? (tw + o * HH) : timw;
        float p = 0.f;
        for (int k = lane; k < HH; k += 32) p += wr[k] * s_h1[k];
        p = warp_sum(p);
        if (lane == 0) out[o] = p + ((o < 16) ? tb[o] : timb[0]);
    }
}

// ---------------- launch ----------------------------------------------------
extern "C" void kernel_launch(void* const* d_in, const int* in_sizes, int n_in,
                              void* d_out, int out_size) {
    const float* x        = (const float*)d_in[0];
    const int*   ei       = (const int*)d_in[1];
    const float* doc      = (const float*)d_in[2];
    const float* pool_w   = (const float*)d_in[3];
    const float* init_w   = (const float*)d_in[4];
    const float* gru_w_ih = (const float*)d_in[5];
    const float* gru_w_hh = (const float*)d_in[6];
    const float* gru_b_ih = (const float*)d_in[7];
    const float* gru_b_hh = (const float*)d_in[8];
    const float* gnn_fc_w = (const float*)d_in[9];
    const float* gnn_fc_b = (const float*)d_in[10];
    const float* doc_fc_w = (const float*)d_in[11];
    const float* doc_fc_b = (const float*)d_in[12];
    const float* ln_g     = (const float*)d_in[13];
    const float* ln_b     = (const float*)d_in[14];
    const float* fus_w    = (const float*)d_in[15];
    const float* fus_b    = (const float*)d_in[16];
    const float* task_w   = (const float*)d_in[17];
    const float* task_b   = (const float*)d_in[18];
    const float* time_w   = (const float*)d_in[19];
    const float* time_b   = (const float*)d_in[20];
    const int E = in_sizes[1] / 2;
    const int* row = ei;
    const int* col = ei + E;
    float* out = (float*)d_out;

    k_zero<<<288, 256>>>(pool_w, doc, doc_fc_w, doc_fc_b);
    k_deg<<<2048, 256>>>(col, E);
    k_acc<<<2048, 256>>>(row, col, E);
    k_xpass<<<592, 256>>>(x, pool_w);
    k_gather<<<400, 512>>>(x, init_w, gru_w_ih, gru_w_hh, gru_b_ih, gru_b_hh,
                           gnn_fc_w, gnn_fc_b, ln_g, ln_b, fus_w, fus_b,
                           task_w, task_b, time_w, time_b, out);
}

// round 11
// speedup vs baseline: 1.5671x; 1.0007x over previous
#include <cuda_runtime.h>
#include <math.h>
#include <stdint.h>

#define NN 200000
#define FF 64
#define HH 256
#define DDIMC 768
#define NBUCK 65536
#define CAND_CAP 2048

// ---------------- scratch (device globals; no allocation allowed) ----------
__device__ int      g_deg[NN];
__device__ float    g_acc[NN];        // sum of dis[col] per row (self-loop added in xpass)
__device__ float    g_score[NN];
__device__ unsigned g_hist[NBUCK];
__device__ float    g_s[FF];
__device__ float    g_dvec[HH];
__device__ float    g_invnorm;
__device__ unsigned g_thresh;
__device__ int      g_cand_cnt;
__device__ unsigned g_done_x;
__device__ unsigned g_done_g;
__device__ unsigned g_cand_key[CAND_CAP];
__device__ int      g_cand_idx[CAND_CAP];

// ---------------- helpers --------------------------------------------------
__device__ __forceinline__ unsigned flipf(float f) {
    unsigned u = __float_as_uint(f);
    return (u & 0x80000000u) ? ~u : (u | 0x80000000u);
}
__device__ __forceinline__ float unflipf(unsigned u) {
    unsigned v = (u & 0x80000000u) ? (u ^ 0x80000000u) : ~u;
    return __uint_as_float(v);
}
__device__ __forceinline__ float warp_sum(float v) {
    for (int o = 16; o; o >>= 1) v += __shfl_xor_sync(0xffffffffu, v, o);
    return v;
}

// ---------------- kernels --------------------------------------------------
// blocks 0..255: init scratch (+ invnorm in block 0); blocks 256..287: doc FC
__global__ void k_zero(const float* __restrict__ pw, const float* __restrict__ doc,
                       const float* __restrict__ dw, const float* __restrict__ db) {
    if (blockIdx.x >= 256) {
        int lane = threadIdx.x & 31;
        int o = (int)(blockIdx.x - 256) * 8 + (threadIdx.x >> 5);   // 0..255
        const float* wr = dw + o * DDIMC;
        float p = 0.f;
        for (int k = lane; k < DDIMC; k += 32) p += wr[k] * doc[k];
        p = warp_sum(p);
        if (lane == 0) {
            float v = p + db[o];
            g_dvec[o] = v > 0.f ? v : 0.f;
        }
        return;
    }
    int i = blockIdx.x * blockDim.x + threadIdx.x;
    const int st = 256 * 256;
    for (int n = i; n < NN; n += st) {
        g_deg[n] = 1;                                       // self-loop folded in
        g_acc[n] = 0.f;
    }
    for (int b = i; b < NBUCK; b += st) g_hist[b] = 0u;
    if (i < FF) g_s[i] = 0.f;
    if (i == 0) { g_cand_cnt = 0; g_done_x = 0u; g_done_g = 0u; }
    if (blockIdx.x == 0 && threadIdx.x < 32) {
        int lane = threadIdx.x;
        float a = pw[lane], b = pw[lane + 32];
        float s = warp_sum(a * a + b * b);
        if (lane == 0) g_invnorm = 1.0f / sqrtf(s);
    }
}

__global__ void k_deg(const int* __restrict__ col, int E) {
    int i = blockIdx.x * blockDim.x + threadIdx.x;
    int st = gridDim.x * blockDim.x;
    if ((E & 3) == 0 && ((((uintptr_t)col) & 15u) == 0)) {
        const int4* c4 = reinterpret_cast<const int4*>(col);
        int nv = E >> 2;
#pragma unroll 4
        for (int v = i; v < nv; v += st) {
            int4 c = c4[v];
            atomicAdd(&g_deg[c.x], 1);
            atomicAdd(&g_deg[c.y], 1);
            atomicAdd(&g_deg[c.z], 1);
            atomicAdd(&g_deg[c.w], 1);
        }
    } else {
        for (int e = i; e < E; e += st) atomicAdd(&g_deg[col[e]], 1);
    }
}

// accsum[row] += rsqrt(deg[col])  (dis[row] factored out; applied in k_xpass)
__global__ void k_acc(const int* __restrict__ row, const int* __restrict__ col, int E) {
    int i = blockIdx.x * blockDim.x + threadIdx.x;
    int st = gridDim.x * blockDim.x;
    if ((E & 3) == 0 && ((((uintptr_t)col) & 15u) == 0) && ((((uintptr_t)row) & 15u) == 0)) {
        const int4* c4 = reinterpret_cast<const int4*>(col);
        const int4* r4 = reinterpret_cast<const int4*>(row);
        int nv = E >> 2;
#pragma unroll 4
        for (int v = i; v < nv; v += st) {
            int4 c = c4[v];
            int4 r = r4[v];
            float d0 = rsqrtf((float)g_deg[c.x]);
            float d1 = rsqrtf((float)g_deg[c.y]);
            float d2 = rsqrtf((float)g_deg[c.z]);
            float d3 = rsqrtf((float)g_deg[c.w]);
            atomicAdd(&g_acc[r.x], d0);
            atomicAdd(&g_acc[r.y], d1);
            atomicAdd(&g_acc[r.z], d2);
            atomicAdd(&g_acc[r.w], d3);
        }
    } else {
        for (int e = i; e < E; e += st)
            atomicAdd(&g_acc[row[e]], rsqrtf((float)g_deg[col[e]]));
    }
}

// Fused pass over x, 8 nodes per warp-iteration (MLP/ILP):
// score + 16-bit-key histogram + s += a[n]*x[n]; last block derives top-64 threshold.
// launch_bounds(256,3): ~85 regs so all 8 float2 loads stay in flight (R10: regs=32 serialized them)
__global__ void __launch_bounds__(256, 3) k_xpass(const float* __restrict__ x,
                                                  const float* __restrict__ pw) {
    __shared__ float ssm[FF];
    __shared__ unsigned chunk[256];
    __shared__ unsigned hc[256];
    __shared__ int sh_last;
    __shared__ int tstar;
    __shared__ unsigned above;
    const int tid = threadIdx.x;
    const int lane = tid & 31;
    const int warp = (blockIdx.x * blockDim.x + tid) >> 5;
    const int nwarps = (gridDim.x * blockDim.x) >> 5;
    const float pw0 = pw[2 * lane], pw1 = pw[2 * lane + 1];
    const float inv = g_invnorm;
    float s0 = 0.f, s1 = 0.f;
    if (tid < FF) ssm[tid] = 0.f;
    __syncthreads();
    const float2* x2 = reinterpret_cast<const float2*>(x);
    for (int g = warp; g < NN / 8; g += nwarps) {           // NN % 8 == 0
        const int base = g * 8;
        float2 xv[8];
        float sc[8];
#pragma unroll
        for (int b = 0; b < 8; b++) xv[b] = x2[(base + b) * 32 + lane];
        // vectorized broadcast loads of deg/acc for the 8 nodes
        int4 dg0 = *reinterpret_cast<const int4*>(&g_deg[base]);
        int4 dg1 = *reinterpret_cast<const int4*>(&g_deg[base + 4]);
        float4 ac0 = *reinterpret_cast<const float4*>(&g_acc[base]);
        float4 ac1 = *reinterpret_cast<const float4*>(&g_acc[base + 4]);
        float aa[8];
        {
            float dv;
            dv = rsqrtf((float)dg0.x); aa[0] = dv * (ac0.x + dv);
            dv = rsqrtf((float)dg0.y); aa[1] = dv * (ac0.y + dv);
            dv = rsqrtf((float)dg0.z); aa[2] = dv * (ac0.z + dv);
            dv = rsqrtf((float)dg0.w); aa[3] = dv * (ac0.w + dv);
            dv = rsqrtf((float)dg1.x); aa[4] = dv * (ac1.x + dv);
            dv = rsqrtf((float)dg1.y); aa[5] = dv * (ac1.y + dv);
            dv = rsqrtf((float)dg1.z); aa[6] = dv * (ac1.z + dv);
            dv = rsqrtf((float)dg1.w); aa[7] = dv * (ac1.w + dv);
        }
#pragma unroll
        for (int b = 0; b < 8; b++) {
            s0 += aa[b] * xv[b].x;
            s1 += aa[b] * xv[b].y;
            sc[b] = xv[b].x * pw0 + xv[b].y * pw1;
        }
#pragma unroll
        for (int o = 16; o; o >>= 1)
#pragma unroll
            for (int b = 0; b < 8; b++) sc[b] += __shfl_xor_sync(0xffffffffu, sc[b], o);
        if (lane == 0) {
#pragma unroll
            for (int b = 0; b < 8; b++) {
                float s = sc[b] * inv;
                g_score[base + b] = s;
                atomicAdd(&g_hist[flipf(s) >> 16], 1u);
            }
        }
    }
    atomicAdd(&ssm[2 * lane], s0);
    atomicAdd(&ssm[2 * lane + 1], s1);
    __syncthreads();
    if (tid < FF) atomicAdd(&g_s[tid], ssm[tid]);
    // ---- last-block-done: compute threshold from completed histogram ----
    __threadfence();
    __syncthreads();
    if (tid == 0) sh_last = (atomicAdd(&g_done_x, 1u) == gridDim.x - 1u) ? 1 : 0;
    __syncthreads();
    if (!sh_last) return;
    __threadfence();
    unsigned s = 0;
    const int base = tid * 256;
#pragma unroll 8
    for (int b = 0; b < 256; b++) s += g_hist[base + b];
    chunk[tid] = s;
    __syncthreads();
    if (tid == 0) {
        unsigned cum = 0;
        int t = 255;
        for (; t > 0; t--) {
            if (cum + chunk[t] >= 64u) break;
            cum += chunk[t];
        }
        tstar = t;
        above = cum;
    }
    __syncthreads();
    hc[tid] = g_hist[tstar * 256 + tid];
    __syncthreads();
    if (tid == 0) {
        unsigned cum = above;
        int b = 255;
        for (; b > 0; b--) {
            cum += hc[b];
            if (cum >= 64u) break;
        }
        g_thresh = ((unsigned)(tstar * 256 + b)) << 16;
    }
}

__device__ __forceinline__ float block_sum_512(float v, volatile float* red) {
    int lane = threadIdx.x & 31, w = threadIdx.x >> 5;
    v = warp_sum(v);
    if (lane == 0) red[w] = v;
    __syncthreads();
    if (threadIdx.x < 32) {
        float r = (threadIdx.x < 16) ? red[threadIdx.x] : 0.f;
        for (int o = 8; o; o >>= 1) r += __shfl_xor_sync(0xffffffffu, r, o);
        if (threadIdx.x == 0) red[0] = r;
    }
    __syncthreads();
    float out = red[0];
    __syncthreads();
    return out;
}

// gather candidates >= threshold; last block: top-64 selection + ENTIRE tail
// (x_tilde -> GRU -> pooled@W -> gnn FC -> layernorm -> fusion FC -> heads)
__global__ void __launch_bounds__(512) k_gather(
    const float* __restrict__ x,
    const float* __restrict__ h0g, const float* __restrict__ wih, const float* __restrict__ whh,
    const float* __restrict__ bih, const float* __restrict__ bhh,
    const float* __restrict__ gw, const float* __restrict__ gb,
    const float* __restrict__ lng, const float* __restrict__ lnb,
    const float* __restrict__ fw, const float* __restrict__ fb,
    const float* __restrict__ tw, const float* __restrict__ tb,
    const float* __restrict__ timw, const float* __restrict__ timb,
    float* __restrict__ out)
{
    __shared__ __align__(16) unsigned char sb[39040];
    // region aliases (ck dead before xt is written)
    unsigned long long* ck  = reinterpret_cast<unsigned long long*>(sb);          // 16384B
    float (*xt)[FF + 1]     = reinterpret_cast<float (*)[FF + 1]>(sb);            // 16640B
    float (*h0)[FF + 1]     = reinterpret_cast<float (*)[FF + 1]>(sb + 16640);    // 16640B
    unsigned long long* sel = reinterpret_cast<unsigned long long*>(sb + 33280);  // 512B
    int*   perm             = reinterpret_cast<int*>(sb + 33792);                 // 256B
    float* ts               = reinterpret_cast<float*>(sb + 34048);               // 256B
    float* s_g              = reinterpret_cast<float*>(sb + 34304);               // 1024B
    float* ln               = reinterpret_cast<float*>(sb + 35328);               // 2048B
    float* s_h1             = reinterpret_cast<float*>(sb + 37376);               // 1024B
    float* ssh              = reinterpret_cast<float*>(sb + 38400);               // 256B
    float* pv               = reinterpret_cast<float*>(sb + 38656);               // 256B
    float* red              = reinterpret_cast<float*>(sb + 38912);               // 64B
    __shared__ int sh_last;

    const int tid = threadIdx.x;
    const int lane = tid & 31;
    const int wp = tid >> 5;                                // 0..15
    {
        int i = blockIdx.x * blockDim.x + tid;
        int st = gridDim.x * blockDim.x;
        unsigned th = g_thresh;
        for (int n = i; n < NN; n += st) {
            unsigned u = flipf(g_score[n]);
            if (u >= th) {
                int p = atomicAdd(&g_cand_cnt, 1);
                if (p < CAND_CAP) {
                    g_cand_key[p] = u;
                    g_cand_idx[p] = n;
                }
            }
        }
    }
    __threadfence();
    __syncthreads();
    if (tid == 0) sh_last = (atomicAdd(&g_done_g, 1u) == gridDim.x - 1u) ? 1 : 0;
    __syncthreads();
    if (!sh_last) return;
    __threadfence();

    // ---- top-64 rank selection (composite keys unique) ----
    int cnt = g_cand_cnt;
    if (cnt > CAND_CAP) cnt = CAND_CAP;
    for (int c = tid; c < cnt; c += 512)
        ck[c] = (((unsigned long long)g_cand_key[c]) << 32) |
                (unsigned)(~(unsigned)g_cand_idx[c]);
    __syncthreads();
    for (int c = tid; c < cnt; c += 512) {
        unsigned long long mine = ck[c];
        int r = 0;
        for (int j = 0; j < cnt; j++) r += (ck[j] > mine) ? 1 : 0;
        if (r < FF) sel[r] = mine;
    }
    __syncthreads();                                        // ck dead after this
    if (tid < FF) {
        unsigned long long c = sel[tid];
        int pidx = (int)(~(unsigned)(c & 0xFFFFFFFFu));
        if (pidx < 0 || pidx >= NN) pidx = 0;               // defensive clamp
        perm[tid] = pidx;
        ts[tid] = tanhf(unflipf((unsigned)(c >> 32)));
    }
    if (tid < FF) ssh[tid] = g_s[tid];
    __syncthreads();
    // build x_tilde (into ck's region) + load h0
    for (int t = tid; t < FF * FF; t += 512) {
        int r = t >> 6, f = t & 63;
        xt[r][f] = x[(long long)perm[r] * FF + f] * ts[r];
        h0[r][f] = h0g[t];
    }
    __syncthreads();

    // ---- GRU: W = (1-z)*tanh(xn + r*hn) + z*h0 ----
    const int i = tid & 63;
    const int q = tid >> 6;                                 // 0..7, uniform within warp
    float Wloc[8];
#pragma unroll
    for (int m = 0; m < 8; m++) {
        int j = q + 8 * m;
        const float* wr = wih + j * FF;
        const float* wz = wih + (j + 64) * FF;
        const float* wn = wih + (j + 128) * FF;
        const float* vr = whh + j * FF;
        const float* vz = whh + (j + 64) * FF;
        const float* vn = whh + (j + 128) * FF;
        float xr = bih[j], xz = bih[j + 64], xn = bih[j + 128];
        float hr = bhh[j], hz = bhh[j + 64], hn = bhh[j + 128];
#pragma unroll 8
        for (int k = 0; k < FF; k++) {
            float xv = xt[i][k], hv = h0[i][k];
            xr += xv * wr[k]; xz += xv * wz[k]; xn += xv * wn[k];
            hr += hv * vr[k]; hz += hv * vz[k]; hn += hv * vn[k];
        }
        float r = 1.f / (1.f + expf(-(xr + hr)));
        float z = 1.f / (1.f + expf(-(xz + hz)));
        float nc = tanhf(xn + r * hn);
        Wloc[m] = (1.f - z) * nc + z * h0[i][j];
    }
    __syncthreads();                                        // all xt reads done
#pragma unroll
    for (int m = 0; m < 8; m++) xt[i][q + 8 * m] = Wloc[m]; // xt now holds W
    __syncthreads();

    // ---- pooled = (s @ W)/N ; g = pooled @ gw.T + gb ----
    if (tid < FF) {
        float a = 0.f;
#pragma unroll 8
        for (int k = 0; k < FF; k++) a += ssh[k] * xt[k][tid];
        pv[tid] = a * (1.0f / (float)NN);
    }
    __syncthreads();
    for (int o = wp; o < HH; o += 16) {
        float2 v = reinterpret_cast<const float2*>(gw)[o * 32 + lane];
        float pp = warp_sum(v.x * pv[2 * lane] + v.y * pv[2 * lane + 1]);
        if (lane == 0) s_g[o] = pp + gb[o];
    }
    __syncthreads();

    // ---- layernorm over [g | d] ----
    float f0 = (tid < HH) ? s_g[tid] : g_dvec[tid - HH];
    float mu = block_sum_512(f0, red) * (1.0f / 512.0f);
    float d0 = f0 - mu;
    float var = block_sum_512(d0 * d0, red) * (1.0f / 512.0f);
    float rstd = rsqrtf(var + 1e-5f);
    ln[tid] = d0 * rstd * lng[tid] + lnb[tid];
    __syncthreads();

    // ---- h1 = relu(ln @ fw.T + fb) ----
    for (int o = wp; o < HH; o += 16) {
        const float4* wr = reinterpret_cast<const float4*>(fw + o * 512);
        float p = 0.f;
#pragma unroll
        for (int it = 0; it < 4; it++) {
            float4 v4 = wr[lane + 32 * it];
            int k = (lane + 32 * it) * 4;
            p += v4.x * ln[k] + v4.y * ln[k + 1] + v4.z * ln[k + 2] + v4.w * ln[k + 3];
        }
        p = warp_sum(p);
        if (lane == 0) {
            float h = p + fb[o];
            s_h1[o] = h > 0.f ? h : 0.f;
        }
    }
    __syncthreads();

    // ---- heads ----
    for (int o = wp; o < 17; o += 16) {
        const float* wr = (o < 16) ? (tw + o * HH) : timw;
        float p = 0.f;
        for (int k = lane; k < HH; k += 32) p += wr[k] * s_h1[k];
        p = warp_sum(p);
        if (lane == 0) out[o] = p + ((o < 16) ? tb[o] : timb[0]);
    }
}

// ---------------- launch ----------------------------------------------------
extern "C" void kernel_launch(void* const* d_in, const int* in_sizes, int n_in,
                              void* d_out, int out_size) {
    const float* x        = (const float*)d_in[0];
    const int*   ei       = (const int*)d_in[1];
    const float* doc      = (const float*)d_in[2];
    const float* pool_w   = (const float*)d_in[3];
    const float* init_w   = (const float*)d_in[4];
    const float* gru_w_ih = (const float*)d_in[5];
    const float* gru_w_hh = (const float*)d_in[6];
    const float* gru_b_ih = (const float*)d_in[7];
    const float* gru_b_hh = (const float*)d_in[8];
    const float* gnn_fc_w = (const float*)d_in[9];
    const float* gnn_fc_b = (const float*)d_in[10];
    const float* doc_fc_w = (const float*)d_in[11];
    const float* doc_fc_b = (const float*)d_in[12];
    const float* ln_g     = (const float*)d_in[13];
    const float* ln_b     = (const float*)d_in[14];
    const float* fus_w    = (const float*)d_in[15];
    const float* fus_b    = (const float*)d_in[16];
    const float* task_w   = (const float*)d_in[17];
    const float* task_b   = (const float*)d_in[18];
    const float* time_w   = (const float*)d_in[19];
    const float* time_b   = (const float*)d_in[20];
    const int E = in_sizes[1] / 2;
    const int* row = ei;
    const int* col = ei + E;
    float* out = (float*)d_out;

    k_zero<<<288, 256>>>(pool_w, doc, doc_fc_w, doc_fc_b);
    k_deg<<<2048, 256>>>(col, E);
    k_acc<<<2048, 256>>>(row, col, E);
    k_xpass<<<444, 256>>>(x, pool_w);
    k_gather<<<400, 512>>>(x, init_w, gru_w_ih, gru_w_hh, gru_b_ih, gru_b_hh,
                           gnn_fc_w, gnn_fc_b, ln_g, ln_b, fus_w, fus_b,
                           task_w, task_b, time_w, time_b, out);
}